// round 13
// baseline (speedup 1.0000x reference)
#include <cuda_runtime.h>
#include <cuda_fp16.h>
#include <cstdint>

#define N_NODES 50000
#define N_EDGES 1600000
#define FEAT    128
#define NUM_RELS 8
#define TILE_M  128
#define N_TILES 391                        /* ceil(50000/128) */
#define N_KEYS  (NUM_RELS * N_NODES)       /* 400000, key = rel*N + dst (rel-major) */
#define SCAN_B  256
#define SB1     ((N_KEYS + SCAN_B - 1) / SCAN_B)   /* 1563 */
#define SB2     ((SB1 + SCAN_B - 1) / SCAN_B)      /* 7 */

// ---------------------------------------------------------------------------
// Device scratch
// ---------------------------------------------------------------------------
__device__ __half    g_hw_h[(size_t)NUM_RELS * N_NODES * FEAT]; // 102.4 MB fp16
__device__ __half    g_x16[(size_t)N_NODES * FEAT];             // 12.8 MB fp16 x
__device__ __half    g_wr_h[(size_t)NUM_RELS * FEAT * FEAT];    // 256 KB fp16, [r][s][k]
__device__ int       g_deg[N_KEYS];
__device__ int       g_cur[N_KEYS];
__device__ int       g_rowstart[N_KEYS + 1];
__device__ int       g_bsum[SB1];
__device__ int       g_bsum2[SB2];
__device__ uint2     g_emeta[N_EDGES];                          // {hw-row byte offset, norm bits}
__device__ int       g_edst[N_EDGES];                           // CSR-ordered dst

// ---------------------------------------------------------------------------
// Helpers
// ---------------------------------------------------------------------------
__device__ __forceinline__ uint32_t smem_to_u32(const void* p) {
    uint32_t a;
    asm("{ .reg .u64 t; cvta.to.shared.u64 t, %1; cvt.u32.u64 %0, t; }" : "=r"(a) : "l"(p));
    return a;
}
__device__ __forceinline__ void cp_async16(uint32_t dst, const void* src) {
    asm volatile("cp.async.cg.shared.global [%0], [%1], 16;"
                 :: "r"(dst), "l"(src) : "memory");
}
__device__ __forceinline__ void cp_async16z(uint32_t dst, const void* src, int srcsize) {
    asm volatile("cp.async.cg.shared.global [%0], [%1], 16, %2;"
                 :: "r"(dst), "l"(src), "r"(srcsize) : "memory");
}
#define CP_COMMIT() asm volatile("cp.async.commit_group;" ::: "memory")
#define CP_WAIT0()  asm volatile("cp.async.wait_group 0;" ::: "memory")

__device__ __forceinline__ void mma_f16(float c[4],
                                        uint32_t a0, uint32_t a1, uint32_t a2, uint32_t a3,
                                        uint32_t b0, uint32_t b1) {
    asm volatile("mma.sync.aligned.m16n8k16.row.col.f32.f16.f16.f32 "
                 "{%0,%1,%2,%3}, {%4,%5,%6,%7}, {%8,%9}, {%0,%1,%2,%3};"
                 : "+f"(c[0]), "+f"(c[1]), "+f"(c[2]), "+f"(c[3])
                 : "r"(a0), "r"(a1), "r"(a2), "r"(a3), "r"(b0), "r"(b1));
}
__device__ __forceinline__ uint2 ldg_u2(const uint2* p) {
    uint2 v;
    asm volatile("ld.global.nc.v2.u32 {%0,%1}, [%2];" : "=r"(v.x), "=r"(v.y) : "l"(p));
    return v;
}

// ---------------------------------------------------------------------------
// Prep: x -> fp16 table
// ---------------------------------------------------------------------------
__global__ __launch_bounds__(256) void prep_x_kernel(const float* __restrict__ x)
{
    int i = blockIdx.x * blockDim.x + threadIdx.x;   // over float4
    if (i >= N_NODES * FEAT / 4) return;
    float4 v = ((const float4*)x)[i];
    __half2 h0 = __floats2half2_rn(v.x, v.y);
    __half2 h1 = __floats2half2_rn(v.z, v.w);
    ((uint2*)g_x16)[i] = make_uint2(*(uint32_t*)&h0, *(uint32_t*)&h1);
}

// Prep: W[r][k][o] -> fp16, column-permuted + transposed to [r][s][k]
//   g(s) = (s/64)*64 + ((s%8)/2)*16 + ((s%64)/8)*2 + (s&1)
__global__ __launch_bounds__(256) void prep_w_kernel(const float* __restrict__ w)
{
    int i = blockIdx.x * blockDim.x + threadIdx.x;
    if (i >= NUM_RELS * FEAT * FEAT) return;
    int r = i >> 14, j = i & 16383;
    int s = j >> 7, k = j & 127;
    int g = (s >> 6) * 64 + ((s & 7) >> 1) * 16 + ((s & 63) >> 3) * 2 + (s & 1);
    g_wr_h[i] = __float2half_rn(w[((size_t)r * FEAT + k) * FEAT + g]);
}

// ---------------------------------------------------------------------------
// Per-relation GEMM: hw[rel] = x @ W[rel] (fp16 mma m16n8k16, fp32 accum)
// ---------------------------------------------------------------------------
#define TS 136
#define BUF_HALFS (128 * TS)
#define GEMM_SMEM (2 * BUF_HALFS * 2)      /* xs + ws, 69632 B */

__global__ __launch_bounds__(256) void rgcn_gemm_rel(int rel)
{
    extern __shared__ __half sm[];
    __half* xs = sm;
    __half* ws = sm + BUF_HALFS;
    const uint32_t xs_u = smem_to_u32(xs);
    const uint32_t ws_u = smem_to_u32(ws);

    const int tid  = threadIdx.x;
    const int row0 = blockIdx.x * TILE_M;

    const __half* wsrc = g_wr_h + (size_t)rel * FEAT * FEAT;
    for (int i = tid; i < 2048; i += 256) {
        int s = i >> 4, c = i & 15;
        cp_async16(ws_u + (uint32_t)(s * TS + c * 8) * 2, wsrc + (size_t)s * FEAT + c * 8);
        int row_g = row0 + s;
        int sz = (row_g < N_NODES) ? 16 : 0;
        int rc = min(row_g, N_NODES - 1);
        cp_async16z(xs_u + (uint32_t)(s * TS + c * 8) * 2, g_x16 + (size_t)rc * FEAT + c * 8, sz);
    }
    CP_COMMIT();
    CP_WAIT0();
    __syncthreads();

    const int wid = tid >> 5, lane = tid & 31;
    const int wm = wid >> 1, wn = wid & 1;
    const int r0 = wm * 32;
    const int n0 = wn * 64;
    const int tr = lane >> 2;
    const int tc2 = (lane & 3) * 2;
    const int tc = lane & 3;

    float c[2][8][4];
    #pragma unroll
    for (int mi = 0; mi < 2; mi++)
        #pragma unroll
        for (int ni = 0; ni < 8; ni++)
            #pragma unroll
            for (int j = 0; j < 4; j++) c[mi][ni][j] = 0.f;

    #pragma unroll
    for (int kk = 0; kk < 8; kk++) {
        const int k0 = kk * 16;
        uint32_t a[2][4], b[8][2];
        #pragma unroll
        for (int mi = 0; mi < 2; mi++) {
            const int rr = r0 + mi * 16 + tr;
            a[mi][0] = *(const uint32_t*)&xs[rr * TS + k0 + tc2];
            a[mi][1] = *(const uint32_t*)&xs[(rr + 8) * TS + k0 + tc2];
            a[mi][2] = *(const uint32_t*)&xs[rr * TS + k0 + tc2 + 8];
            a[mi][3] = *(const uint32_t*)&xs[(rr + 8) * TS + k0 + tc2 + 8];
        }
        #pragma unroll
        for (int ni = 0; ni < 8; ni++) {
            const int nn = n0 + ni * 8 + tr;
            b[ni][0] = *(const uint32_t*)&ws[nn * TS + k0 + tc2];
            b[ni][1] = *(const uint32_t*)&ws[nn * TS + k0 + tc2 + 8];
        }
        #pragma unroll
        for (int mi = 0; mi < 2; mi++)
            #pragma unroll
            for (int ni = 0; ni < 8; ni++)
                mma_f16(c[mi][ni], a[mi][0], a[mi][1], a[mi][2], a[mi][3],
                        b[ni][0], b[ni][1]);
    }

    #pragma unroll
    for (int mi = 0; mi < 2; mi++) {
        #pragma unroll
        for (int p = 0; p < 2; p++) {
            const int row = row0 + r0 + mi * 16 + tr + p * 8;
            if (row < N_NODES) {
                uint32_t h[8];
                #pragma unroll
                for (int ni = 0; ni < 8; ni++) {
                    __half2 hh = __floats2half2_rn(c[mi][ni][2 * p], c[mi][ni][2 * p + 1]);
                    h[ni] = *(uint32_t*)&hh;
                }
                uint4* dst = (uint4*)(g_hw_h + ((size_t)rel * N_NODES + row) * FEAT + n0 + tc * 16);
                dst[0] = make_uint4(h[0], h[1], h[2], h[3]);
                dst[1] = make_uint4(h[4], h[5], h[6], h[7]);
            }
        }
    }
}

// ---------------------------------------------------------------------------
// CSR build over key = rel*N_NODES + dst  (rel-major, dst-sorted inside)
// ---------------------------------------------------------------------------
__global__ __launch_bounds__(256) void csr_zero_kernel()
{
    int i = blockIdx.x * blockDim.x + threadIdx.x;
    if (i < N_KEYS) { g_deg[i] = 0; g_cur[i] = 0; }
}

__global__ __launch_bounds__(512) void csr_hist_kernel(
    const int* __restrict__ dst, const int* __restrict__ rel)
{
    int e = blockIdx.x * blockDim.x + threadIdx.x;
    if (e < N_EDGES) atomicAdd(&g_deg[__ldg(rel + e) * N_NODES + __ldg(dst + e)], 1);
}

__global__ __launch_bounds__(SCAN_B) void csr_scan_block_kernel()
{
    __shared__ int sh[SCAN_B];
    int i = blockIdx.x * SCAN_B + threadIdx.x;
    int v = (i < N_KEYS) ? g_deg[i] : 0;
    sh[threadIdx.x] = v;
    __syncthreads();
    #pragma unroll
    for (int o = 1; o < SCAN_B; o <<= 1) {
        int t = (threadIdx.x >= o) ? sh[threadIdx.x - o] : 0;
        __syncthreads();
        sh[threadIdx.x] += t;
        __syncthreads();
    }
    if (i < N_KEYS) g_rowstart[i] = sh[threadIdx.x] - v;
    if (threadIdx.x == SCAN_B - 1) g_bsum[blockIdx.x] = sh[SCAN_B - 1];
}

__global__ __launch_bounds__(SCAN_B) void csr_scan_bsum_kernel()
{
    __shared__ int sh[SCAN_B];
    int i = blockIdx.x * SCAN_B + threadIdx.x;
    int v = (i < SB1) ? g_bsum[i] : 0;
    sh[threadIdx.x] = v;
    __syncthreads();
    #pragma unroll
    for (int o = 1; o < SCAN_B; o <<= 1) {
        int t = (threadIdx.x >= o) ? sh[threadIdx.x - o] : 0;
        __syncthreads();
        sh[threadIdx.x] += t;
        __syncthreads();
    }
    if (i < SB1) g_bsum[i] = sh[threadIdx.x] - v;
    if (threadIdx.x == SCAN_B - 1) g_bsum2[blockIdx.x] = sh[SCAN_B - 1];
}

__global__ __launch_bounds__(SCAN_B) void csr_scan_bsum2_kernel()
{
    __shared__ int sh[SCAN_B];
    int v = (threadIdx.x < SB2) ? g_bsum2[threadIdx.x] : 0;
    sh[threadIdx.x] = v;
    __syncthreads();
    #pragma unroll
    for (int o = 1; o < SCAN_B; o <<= 1) {
        int t = (threadIdx.x >= o) ? sh[threadIdx.x - o] : 0;
        __syncthreads();
        sh[threadIdx.x] += t;
        __syncthreads();
    }
    if (threadIdx.x < SB2) g_bsum2[threadIdx.x] = sh[threadIdx.x] - v;
}

__global__ __launch_bounds__(256) void csr_add_offsets_kernel()
{
    int i = blockIdx.x * blockDim.x + threadIdx.x;
    if (i < N_KEYS) g_rowstart[i] += g_bsum[i >> 8] + g_bsum2[i >> 16];
    if (i == 0) g_rowstart[N_KEYS] = N_EDGES;
}

__global__ __launch_bounds__(512) void csr_permute_kernel(
    const int* __restrict__ src, const int* __restrict__ dst,
    const int* __restrict__ rel, const float* __restrict__ norm)
{
    int e = blockIdx.x * blockDim.x + threadIdx.x;
    if (e >= N_EDGES) return;
    int r = __ldg(rel + e);
    int d = __ldg(dst + e);
    int key = r * N_NODES + d;
    int pos = atomicAdd(&g_cur[key], 1);
    int p = g_rowstart[key] + pos;
    uint32_t off = (uint32_t)((r * N_NODES + __ldg(src + e)) * (FEAT * 2));
    g_emeta[p] = make_uint2(off, __float_as_uint(__ldg(norm + e)));
    g_edst[p]  = d;
}

// ---------------------------------------------------------------------------
// Per-relation aggregate: warp per 32-edge block of rel r's range (grid-stride
// over blocks; range read on device). Gathers hit the fresh 12.8 MB hw[r]
// slice (L2-hot). Segment flushes via red.global.add.v4.f32. Partial tail
// block padded with norm=0 / row-0 metadata (zero contribution).
// ---------------------------------------------------------------------------
#define AGG_CTAS 320

__global__ __launch_bounds__(256) void rgcn_aggregate_rel(int rel, float* __restrict__ out)
{
    const int gwarp  = (blockIdx.x * blockDim.x + threadIdx.x) >> 5;
    const int nwarps = gridDim.x * (blockDim.x >> 5);
    const int lane   = threadIdx.x & 31;

    const int ebeg = __ldg(&g_rowstart[rel * N_NODES]);
    const int eend = __ldg(&g_rowstart[(rel + 1) * N_NODES]);
    const int nblk = (eend - ebeg + 31) >> 5;

    const char* hwb = (const char*)g_hw_h;

    for (int blk = gwarp; blk < nblk; blk += nwarps) {
        const int base = ebeg + blk * 32;
        const int m = min(32, eend - base);

        uint2 mt = make_uint2(0u, 0u);
        int d = 0;
        if (lane < m) {
            mt = ldg_u2(&g_emeta[base + lane]);
            d  = __ldg(&g_edst[base + lane]);
        }

        const int dnext = __shfl_down_sync(0xffffffffu, d, 1);
        const uint32_t fmask = __ballot_sync(0xffffffffu, (lane == 31) || (d != dnext));

        uint2 pre[8];
        #pragma unroll
        for (int j = 0; j < 8; j++) {
            uint32_t o = __shfl_sync(0xffffffffu, mt.x, j);
            pre[j] = ldg_u2(((const uint2*)(hwb + o)) + lane);
        }

        float4 acc = make_float4(0.f, 0.f, 0.f, 0.f);

        #pragma unroll
        for (int i = 0; i < 32; i++) {
            const float nm  = __uint_as_float(__shfl_sync(0xffffffffu, mt.y, i));
            const uint2 cur = pre[i & 7];
            if (i + 8 < 32) {
                uint32_t o = __shfl_sync(0xffffffffu, mt.x, i + 8);
                pre[i & 7] = ldg_u2(((const uint2*)(hwb + o)) + lane);
            }
            float2 f0 = __half22float2(*(const __half2*)&cur.x);
            float2 f1 = __half22float2(*(const __half2*)&cur.y);
            acc.x = fmaf(f0.x, nm, acc.x);
            acc.y = fmaf(f0.y, nm, acc.y);
            acc.z = fmaf(f1.x, nm, acc.z);
            acc.w = fmaf(f1.y, nm, acc.w);

            if ((fmask >> i) & 1u) {
                const int dd = __shfl_sync(0xffffffffu, d, i);
                float* o4 = out + (size_t)dd * FEAT + lane * 4;
                asm volatile("red.global.add.v4.f32 [%0], {%1,%2,%3,%4};"
                             :: "l"(o4), "f"(acc.x), "f"(acc.y), "f"(acc.z), "f"(acc.w)
                             : "memory");
                acc = make_float4(0.f, 0.f, 0.f, 0.f);
            }
        }
    }
}

// ---------------------------------------------------------------------------
// Epilogue: out = relu(out + bias)
// ---------------------------------------------------------------------------
__global__ __launch_bounds__(256) void rgcn_bias_relu_kernel(
    float* __restrict__ out, const float* __restrict__ bias)
{
    const int i = blockIdx.x * blockDim.x + threadIdx.x;
    if (i >= N_NODES * FEAT / 4) return;
    float4 v = ((float4*)out)[i];
    float4 b = ((const float4*)bias)[i & 31];
    v.x = fmaxf(v.x + b.x, 0.f);
    v.y = fmaxf(v.y + b.y, 0.f);
    v.z = fmaxf(v.z + b.z, 0.f);
    v.w = fmaxf(v.w + b.w, 0.f);
    ((float4*)out)[i] = v;
}

// ---------------------------------------------------------------------------
// Launch: 3 streams. main: prep + 8 per-rel GEMMs. s2: CSR build. s3: memset +
// per-rel aggregates, each gated on its GEMM's event + CSR done.
// ---------------------------------------------------------------------------
extern "C" void kernel_launch(void* const* d_in, const int* in_sizes, int n_in,
                              void* d_out, int out_size)
{
    const float* x      = (const float*)d_in[0];
    const float* norm   = (const float*)d_in[1];
    const float* weight = (const float*)d_in[2];
    const float* bias   = (const float*)d_in[3];
    const int*   src    = (const int*)d_in[4];
    const int*   dst    = (const int*)d_in[5];
    const int*   rel    = (const int*)d_in[6];
    float*       out    = (float*)d_out;

    cudaFuncSetAttribute(rgcn_gemm_rel, cudaFuncAttributeMaxDynamicSharedMemorySize, GEMM_SMEM);

    cudaStream_t s2, s3;
    cudaStreamCreateWithFlags(&s2, cudaStreamNonBlocking);
    cudaStreamCreateWithFlags(&s3, cudaStreamNonBlocking);
    cudaEvent_t e_fork, e_csr, e_agg, e_g[NUM_RELS];
    cudaEventCreateWithFlags(&e_fork, cudaEventDisableTiming);
    cudaEventCreateWithFlags(&e_csr, cudaEventDisableTiming);
    cudaEventCreateWithFlags(&e_agg, cudaEventDisableTiming);
    for (int r = 0; r < NUM_RELS; r++) cudaEventCreateWithFlags(&e_g[r], cudaEventDisableTiming);

    // main: preps
    prep_w_kernel<<<(NUM_RELS * FEAT * FEAT + 255) / 256, 256>>>(weight);
    prep_x_kernel<<<(N_NODES * FEAT / 4 + 255) / 256, 256>>>(x);

    cudaEventRecord(e_fork, 0);
    cudaStreamWaitEvent(s2, e_fork, 0);
    cudaStreamWaitEvent(s3, e_fork, 0);

    // s2: CSR build (rel-major keys)
    csr_zero_kernel<<<(N_KEYS + 255) / 256, 256, 0, s2>>>();
    csr_hist_kernel<<<(N_EDGES + 511) / 512, 512, 0, s2>>>(dst, rel);
    csr_scan_block_kernel<<<SB1, SCAN_B, 0, s2>>>();
    csr_scan_bsum_kernel<<<SB2, SCAN_B, 0, s2>>>();
    csr_scan_bsum2_kernel<<<1, SCAN_B, 0, s2>>>();
    csr_add_offsets_kernel<<<(N_KEYS + 255) / 256, 256, 0, s2>>>();
    csr_permute_kernel<<<(N_EDGES + 511) / 512, 512, 0, s2>>>(src, dst, rel, norm);
    cudaEventRecord(e_csr, s2);

    // s3: zero the accumulation target while CSR/GEMMs run
    cudaMemsetAsync(out, 0, (size_t)N_NODES * FEAT * sizeof(float), s3);

    // main: per-rel GEMMs, each followed by an event
    for (int r = 0; r < NUM_RELS; r++) {
        rgcn_gemm_rel<<<N_TILES, 256, GEMM_SMEM>>>(r);
        cudaEventRecord(e_g[r], 0);
    }

    // s3: per-rel aggregates, gated on CSR + their GEMM
    cudaStreamWaitEvent(s3, e_csr, 0);
    for (int r = 0; r < NUM_RELS; r++) {
        cudaStreamWaitEvent(s3, e_g[r], 0);
        rgcn_aggregate_rel<<<AGG_CTAS, 256, 0, s3>>>(r, out);
    }
    cudaEventRecord(e_agg, s3);

    // main: epilogue after all aggregates
    cudaStreamWaitEvent(0, e_agg, 0);
    rgcn_bias_relu_kernel<<<(N_NODES * FEAT / 4 + 255) / 256, 256>>>(out, bias);

    for (int r = 0; r < NUM_RELS; r++) cudaEventDestroy(e_g[r]);
    cudaEventDestroy(e_fork);
    cudaEventDestroy(e_csr);
    cudaEventDestroy(e_agg);
    cudaStreamDestroy(s2);
    cudaStreamDestroy(s3);
}

// round 14
// speedup vs baseline: 1.4196x; 1.4196x over previous
#include <cuda_runtime.h>
#include <cuda_fp16.h>
#include <cstdint>

#define N_NODES 50000
#define N_EDGES 1600000
#define FEAT    128
#define NUM_RELS 8
#define TILE_M  128
#define N_TILES 391                        /* ceil(50000/128) */
#define N_KEYS  (N_NODES * NUM_RELS)       /* 400000, key = dst*8 + rel */
#define SCAN_B  256
#define SB1     ((N_KEYS + SCAN_B - 1) / SCAN_B)   /* 1563 */
#define SB2     ((SB1 + SCAN_B - 1) / SCAN_B)      /* 7 */
#define N_EBLK  (N_EDGES / 32)             /* 50000 full 32-edge blocks */

// ---------------------------------------------------------------------------
// Device scratch
// ---------------------------------------------------------------------------
__device__ __half    g_hw_h[(size_t)NUM_RELS * N_NODES * FEAT]; // 102.4 MB fp16
__device__ __half    g_wr_h[(size_t)NUM_RELS * FEAT * FEAT];    // 256 KB fp16, [r][s][k]
__device__ int       g_deg[N_KEYS];
__device__ int       g_cur[N_KEYS];
__device__ int       g_rowstart[N_KEYS + 1];
__device__ int       g_bsum[SB1];
__device__ int       g_bsum2[SB2];
__device__ uint2     g_emeta[N_EDGES];                          // {hw-row byte offset, norm bits}
__device__ int       g_edst[N_EDGES];                           // CSR-ordered dst

// ---------------------------------------------------------------------------
// Helpers
// ---------------------------------------------------------------------------
__device__ __forceinline__ uint32_t smem_to_u32(const void* p) {
    uint32_t a;
    asm("{ .reg .u64 t; cvta.to.shared.u64 t, %1; cvt.u32.u64 %0, t; }" : "=r"(a) : "l"(p));
    return a;
}
__device__ __forceinline__ void cp_async16(uint32_t dst, const void* src) {
    asm volatile("cp.async.cg.shared.global [%0], [%1], 16;"
                 :: "r"(dst), "l"(src) : "memory");
}
#define CP_COMMIT() asm volatile("cp.async.commit_group;" ::: "memory")
#define CP_WAIT1()  asm volatile("cp.async.wait_group 1;" ::: "memory")
#define CP_WAIT0()  asm volatile("cp.async.wait_group 0;" ::: "memory")

__device__ __forceinline__ void mma_f16(float c[4],
                                        uint32_t a0, uint32_t a1, uint32_t a2, uint32_t a3,
                                        uint32_t b0, uint32_t b1) {
    asm volatile("mma.sync.aligned.m16n8k16.row.col.f32.f16.f16.f32 "
                 "{%0,%1,%2,%3}, {%4,%5,%6,%7}, {%8,%9}, {%0,%1,%2,%3};"
                 : "+f"(c[0]), "+f"(c[1]), "+f"(c[2]), "+f"(c[3])
                 : "r"(a0), "r"(a1), "r"(a2), "r"(a3), "r"(b0), "r"(b1));
}
__device__ __forceinline__ uint2 ldg_u2(const uint2* p) {
    uint2 v;
    asm volatile("ld.global.nc.v2.u32 {%0,%1}, [%2];" : "=r"(v.x), "=r"(v.y) : "l"(p));
    return v;
}

// ---------------------------------------------------------------------------
// Prep: W[r][k][o] -> fp16, column-permuted + transposed to [r][s][k]
//   g(s) = (s/64)*64 + ((s%8)/2)*16 + ((s%64)/8)*2 + (s&1)
// ---------------------------------------------------------------------------
__global__ __launch_bounds__(256) void prep_w_kernel(const float* __restrict__ w)
{
    int i = blockIdx.x * blockDim.x + threadIdx.x;
    if (i >= NUM_RELS * FEAT * FEAT) return;
    int r = i >> 14, j = i & 16383;
    int s = j >> 7, k = j & 127;
    int g = (s >> 6) * 64 + ((s & 7) >> 1) * 16 + ((s & 63) >> 3) * 2 + (s & 1);
    g_wr_h[i] = __float2half_rn(w[((size_t)r * FEAT + k) * FEAT + g]);
}

// ---------------------------------------------------------------------------
// GEMM via mma.sync fp16 (m16n8k16). Unchanged from R8/R12.
// ---------------------------------------------------------------------------
#define XS_STRIDE 136
#define WS_STRIDE 136
#define XS_HALFS (128 * XS_STRIDE)
#define WS_HALFS (128 * WS_STRIDE)
#define GEMM_SMEM ((XS_HALFS + 2 * WS_HALFS) * 2)

__global__ __launch_bounds__(256) void rgcn_gemm_mma(const float* __restrict__ x)
{
    extern __shared__ __half sm[];
    __half* xs = sm;
    __half* ws = sm + XS_HALFS;
    const uint32_t ws_u = smem_to_u32(ws);

    const int tid  = threadIdx.x;
    const int tile = blockIdx.x;
    const int row0 = tile * TILE_M;

    for (int i = tid; i < 2048; i += 256) {
        int s = i >> 4, c = i & 15;
        cp_async16(ws_u + (uint32_t)(s * WS_STRIDE + c * 8) * 2,
                   g_wr_h + (size_t)s * FEAT + c * 8);
    }
    CP_COMMIT();
    for (int i = tid; i < 2048; i += 256) {
        int s = i >> 4, c = i & 15;
        cp_async16(ws_u + (uint32_t)(WS_HALFS + s * WS_STRIDE + c * 8) * 2,
                   g_wr_h + (size_t)FEAT * FEAT + (size_t)s * FEAT + c * 8);
    }
    CP_COMMIT();

    for (int i = tid; i < 4096; i += 256) {
        int row = i >> 5, c = i & 31;
        float4 v = make_float4(0.f, 0.f, 0.f, 0.f);
        if (row0 + row < N_NODES) v = ((const float4*)x)[(size_t)(row0 + row) * 32 + c];
        __half2 h0 = __floats2half2_rn(v.x, v.y);
        __half2 h1 = __floats2half2_rn(v.z, v.w);
        uint2* d = (uint2*)&xs[row * XS_STRIDE + c * 4];
        *d = make_uint2(*(uint32_t*)&h0, *(uint32_t*)&h1);
    }

    CP_WAIT1();
    __syncthreads();

    const int wid = tid >> 5, lane = tid & 31;
    const int wm = wid >> 1, wn = wid & 1;
    const int r0 = wm * 32;
    const int n0 = wn * 64;
    const int tr = lane >> 2;
    const int tc2 = (lane & 3) * 2;
    const int tc = lane & 3;

    for (int rel = 0; rel < NUM_RELS; rel++) {
        const __half* wb = ws + (rel & 1) * WS_HALFS;

        float c[2][8][4];
        #pragma unroll
        for (int mi = 0; mi < 2; mi++)
            #pragma unroll
            for (int ni = 0; ni < 8; ni++)
                #pragma unroll
                for (int j = 0; j < 4; j++) c[mi][ni][j] = 0.f;

        #pragma unroll
        for (int kk = 0; kk < 8; kk++) {
            const int k0 = kk * 16;
            uint32_t a[2][4], b[8][2];
            #pragma unroll
            for (int mi = 0; mi < 2; mi++) {
                const int rr = r0 + mi * 16 + tr;
                a[mi][0] = *(const uint32_t*)&xs[rr * XS_STRIDE + k0 + tc2];
                a[mi][1] = *(const uint32_t*)&xs[(rr + 8) * XS_STRIDE + k0 + tc2];
                a[mi][2] = *(const uint32_t*)&xs[rr * XS_STRIDE + k0 + tc2 + 8];
                a[mi][3] = *(const uint32_t*)&xs[(rr + 8) * XS_STRIDE + k0 + tc2 + 8];
            }
            #pragma unroll
            for (int ni = 0; ni < 8; ni++) {
                const int nn = n0 + ni * 8 + tr;
                b[ni][0] = *(const uint32_t*)&wb[nn * WS_STRIDE + k0 + tc2];
                b[ni][1] = *(const uint32_t*)&wb[nn * WS_STRIDE + k0 + tc2 + 8];
            }
            #pragma unroll
            for (int mi = 0; mi < 2; mi++)
                #pragma unroll
                for (int ni = 0; ni < 8; ni++)
                    mma_f16(c[mi][ni], a[mi][0], a[mi][1], a[mi][2], a[mi][3],
                            b[ni][0], b[ni][1]);
        }

        __syncthreads();

        if (rel + 2 < NUM_RELS) {
            for (int i = tid; i < 2048; i += 256) {
                int s = i >> 4, cc = i & 15;
                cp_async16(ws_u + (uint32_t)((rel & 1) * WS_HALFS + s * WS_STRIDE + cc * 8) * 2,
                           g_wr_h + (size_t)(rel + 2) * FEAT * FEAT + (size_t)s * FEAT + cc * 8);
            }
            CP_COMMIT();
        }

        #pragma unroll
        for (int mi = 0; mi < 2; mi++) {
            #pragma unroll
            for (int p = 0; p < 2; p++) {
                const int row = row0 + r0 + mi * 16 + tr + p * 8;
                if (row < N_NODES) {
                    uint32_t h[8];
                    #pragma unroll
                    for (int ni = 0; ni < 8; ni++) {
                        __half2 hh = __floats2half2_rn(c[mi][ni][2 * p], c[mi][ni][2 * p + 1]);
                        h[ni] = *(uint32_t*)&hh;
                    }
                    uint4* dst = (uint4*)(g_hw_h + ((size_t)rel * N_NODES + row) * FEAT + n0 + tc * 16);
                    dst[0] = make_uint4(h[0], h[1], h[2], h[3]);
                    dst[1] = make_uint4(h[4], h[5], h[6], h[7]);
                }
            }
        }

        if (rel + 1 < NUM_RELS) {
            if (rel + 2 < NUM_RELS) { CP_WAIT1(); }
            else                    { CP_WAIT0(); }
            __syncthreads();
        }
    }
}

// ---------------------------------------------------------------------------
// CSR build over key = dst*8 + rel  (edge list dst-major, rel-sorted inside)
// ---------------------------------------------------------------------------
__global__ __launch_bounds__(256) void csr_zero_kernel()
{
    int i = blockIdx.x * blockDim.x + threadIdx.x;
    if (i < N_KEYS) { g_deg[i] = 0; g_cur[i] = 0; }
}

__global__ __launch_bounds__(512) void csr_hist_kernel(
    const int* __restrict__ dst, const int* __restrict__ rel)
{
    int e = blockIdx.x * blockDim.x + threadIdx.x;
    if (e < N_EDGES) atomicAdd(&g_deg[__ldg(dst + e) * NUM_RELS + __ldg(rel + e)], 1);
}

__global__ __launch_bounds__(SCAN_B) void csr_scan_block_kernel()
{
    __shared__ int sh[SCAN_B];
    int i = blockIdx.x * SCAN_B + threadIdx.x;
    int v = (i < N_KEYS) ? g_deg[i] : 0;
    sh[threadIdx.x] = v;
    __syncthreads();
    #pragma unroll
    for (int o = 1; o < SCAN_B; o <<= 1) {
        int t = (threadIdx.x >= o) ? sh[threadIdx.x - o] : 0;
        __syncthreads();
        sh[threadIdx.x] += t;
        __syncthreads();
    }
    if (i < N_KEYS) g_rowstart[i] = sh[threadIdx.x] - v;
    if (threadIdx.x == SCAN_B - 1) g_bsum[blockIdx.x] = sh[SCAN_B - 1];
}

__global__ __launch_bounds__(SCAN_B) void csr_scan_bsum_kernel()
{
    __shared__ int sh[SCAN_B];
    int i = blockIdx.x * SCAN_B + threadIdx.x;
    int v = (i < SB1) ? g_bsum[i] : 0;
    sh[threadIdx.x] = v;
    __syncthreads();
    #pragma unroll
    for (int o = 1; o < SCAN_B; o <<= 1) {
        int t = (threadIdx.x >= o) ? sh[threadIdx.x - o] : 0;
        __syncthreads();
        sh[threadIdx.x] += t;
        __syncthreads();
    }
    if (i < SB1) g_bsum[i] = sh[threadIdx.x] - v;
    if (threadIdx.x == SCAN_B - 1) g_bsum2[blockIdx.x] = sh[SCAN_B - 1];
}

__global__ __launch_bounds__(SCAN_B) void csr_scan_bsum2_kernel()
{
    __shared__ int sh[SCAN_B];
    int v = (threadIdx.x < SB2) ? g_bsum2[threadIdx.x] : 0;
    sh[threadIdx.x] = v;
    __syncthreads();
    #pragma unroll
    for (int o = 1; o < SCAN_B; o <<= 1) {
        int t = (threadIdx.x >= o) ? sh[threadIdx.x - o] : 0;
        __syncthreads();
        sh[threadIdx.x] += t;
        __syncthreads();
    }
    if (threadIdx.x < SB2) g_bsum2[threadIdx.x] = sh[threadIdx.x] - v;
}

__global__ __launch_bounds__(256) void csr_add_offsets_kernel()
{
    int i = blockIdx.x * blockDim.x + threadIdx.x;
    if (i < N_KEYS) g_rowstart[i] += g_bsum[i >> 8] + g_bsum2[i >> 16];
    if (i == 0) g_rowstart[N_KEYS] = N_EDGES;
}

__global__ __launch_bounds__(512) void csr_permute_kernel(
    const int* __restrict__ src, const int* __restrict__ dst,
    const int* __restrict__ rel, const float* __restrict__ norm)
{
    int e = blockIdx.x * blockDim.x + threadIdx.x;
    if (e >= N_EDGES) return;
    int r = __ldg(rel + e);
    int d = __ldg(dst + e);
    int key = d * NUM_RELS + r;
    int pos = atomicAdd(&g_cur[key], 1);
    int p = g_rowstart[key] + pos;
    uint32_t off = (uint32_t)((r * N_NODES + __ldg(src + e)) * (FEAT * 2));
    g_emeta[p] = make_uint2(off, __float_as_uint(__ldg(norm + e)));
    g_edst[p]  = d;
}

// ---------------------------------------------------------------------------
// Aggregate: warp per 32-edge block of the dst-sorted edge list. Depth-16
// LDG.64 ring (16 outstanding warp-loads; M_max=55 headroom). Node boundary
// flushes via red.global.add.v4.f32 (~2/block).
// ---------------------------------------------------------------------------
__global__ __launch_bounds__(256) void rgcn_aggregate_kernel(float* __restrict__ out)
{
    const int blk  = (blockIdx.x * blockDim.x + threadIdx.x) >> 5;
    const int lane = threadIdx.x & 31;
    if (blk >= N_EBLK) return;

    const int base = blk * 32;
    const uint2 mt = ldg_u2(&g_emeta[base + lane]);
    const int   d  = __ldg(&g_edst[base + lane]);

    // flush mask: last edge of each node segment within the block
    const int dnext = __shfl_down_sync(0xffffffffu, d, 1);
    const uint32_t fmask = __ballot_sync(0xffffffffu, (lane == 31) || (d != dnext));

    const char* hwb = (const char*)g_hw_h;

    uint2 pre[16];
    #pragma unroll
    for (int j = 0; j < 16; j++) {
        uint32_t o = __shfl_sync(0xffffffffu, mt.x, j);
        pre[j] = ldg_u2(((const uint2*)(hwb + o)) + lane);
    }

    float4 acc = make_float4(0.f, 0.f, 0.f, 0.f);

    #pragma unroll
    for (int i = 0; i < 32; i++) {
        const float nm  = __uint_as_float(__shfl_sync(0xffffffffu, mt.y, i));
        const uint2 cur = pre[i & 15];
        if (i + 16 < 32) {
            uint32_t o = __shfl_sync(0xffffffffu, mt.x, i + 16);
            pre[i & 15] = ldg_u2(((const uint2*)(hwb + o)) + lane);
        }
        float2 f0 = __half22float2(*(const __half2*)&cur.x);
        float2 f1 = __half22float2(*(const __half2*)&cur.y);
        acc.x = fmaf(f0.x, nm, acc.x);
        acc.y = fmaf(f0.y, nm, acc.y);
        acc.z = fmaf(f1.x, nm, acc.z);
        acc.w = fmaf(f1.y, nm, acc.w);

        if ((fmask >> i) & 1u) {
            const int dd = __shfl_sync(0xffffffffu, d, i);
            float* o4 = out + (size_t)dd * FEAT + lane * 4;
            asm volatile("red.global.add.v4.f32 [%0], {%1,%2,%3,%4};"
                         :: "l"(o4), "f"(acc.x), "f"(acc.y), "f"(acc.z), "f"(acc.w)
                         : "memory");
            acc = make_float4(0.f, 0.f, 0.f, 0.f);
        }
    }
}

// ---------------------------------------------------------------------------
// Epilogue: out = relu(out + bias)
// ---------------------------------------------------------------------------
__global__ __launch_bounds__(256) void rgcn_bias_relu_kernel(
    float* __restrict__ out, const float* __restrict__ bias)
{
    const int i = blockIdx.x * blockDim.x + threadIdx.x;
    if (i >= N_NODES * FEAT / 4) return;
    float4 v = ((float4*)out)[i];
    float4 b = ((const float4*)bias)[i & 31];
    v.x = fmaxf(v.x + b.x, 0.f);
    v.y = fmaxf(v.y + b.y, 0.f);
    v.z = fmaxf(v.z + b.z, 0.f);
    v.w = fmaxf(v.w + b.w, 0.f);
    ((float4*)out)[i] = v;
}

// ---------------------------------------------------------------------------
// Launch: s2 = CSR chain, s3 = memset, main = prep + GEMM. Join before
// aggregate + epilogue.
// ---------------------------------------------------------------------------
extern "C" void kernel_launch(void* const* d_in, const int* in_sizes, int n_in,
                              void* d_out, int out_size)
{
    const float* x      = (const float*)d_in[0];
    const float* norm   = (const float*)d_in[1];
    const float* weight = (const float*)d_in[2];
    const float* bias   = (const float*)d_in[3];
    const int*   src    = (const int*)d_in[4];
    const int*   dst    = (const int*)d_in[5];
    const int*   rel    = (const int*)d_in[6];
    float*       out    = (float*)d_out;

    cudaFuncSetAttribute(rgcn_gemm_mma, cudaFuncAttributeMaxDynamicSharedMemorySize, GEMM_SMEM);

    cudaStream_t s2, s3;
    cudaStreamCreateWithFlags(&s2, cudaStreamNonBlocking);
    cudaStreamCreateWithFlags(&s3, cudaStreamNonBlocking);
    cudaEvent_t e_fork, e_csr, e_ms;
    cudaEventCreateWithFlags(&e_fork, cudaEventDisableTiming);
    cudaEventCreateWithFlags(&e_csr, cudaEventDisableTiming);
    cudaEventCreateWithFlags(&e_ms, cudaEventDisableTiming);

    // launch 1 (main)
    prep_w_kernel<<<(NUM_RELS * FEAT * FEAT + 255) / 256, 256>>>(weight);

    cudaEventRecord(e_fork, 0);
    cudaStreamWaitEvent(s2, e_fork, 0);
    cudaStreamWaitEvent(s3, e_fork, 0);

    // s3: zero accumulation target (off critical path)
    cudaMemsetAsync(out, 0, (size_t)N_NODES * FEAT * sizeof(float), s3);
    cudaEventRecord(e_ms, s3);

    // s2: CSR build
    csr_zero_kernel<<<(N_KEYS + 255) / 256, 256, 0, s2>>>();
    csr_hist_kernel<<<(N_EDGES + 511) / 512, 512, 0, s2>>>(dst, rel);
    csr_scan_block_kernel<<<SB1, SCAN_B, 0, s2>>>();
    csr_scan_bsum_kernel<<<SB2, SCAN_B, 0, s2>>>();
    csr_scan_bsum2_kernel<<<1, SCAN_B, 0, s2>>>();
    csr_add_offsets_kernel<<<(N_KEYS + 255) / 256, 256, 0, s2>>>();
    csr_permute_kernel<<<(N_EDGES + 511) / 512, 512, 0, s2>>>(src, dst, rel, norm);
    cudaEventRecord(e_csr, s2);

    // main: GEMM
    rgcn_gemm_mma<<<N_TILES, 256, GEMM_SMEM>>>(x);

    // join, then edge-block aggregate + epilogue
    cudaStreamWaitEvent(0, e_csr, 0);
    cudaStreamWaitEvent(0, e_ms, 0);
    const int ablocks = (N_EBLK * 32 + 255) / 256;
    rgcn_aggregate_kernel<<<ablocks, 256>>>(out);
    rgcn_bias_relu_kernel<<<(N_NODES * FEAT / 4 + 255) / 256, 256>>>(out, bias);

    cudaEventDestroy(e_fork);
    cudaEventDestroy(e_csr);
    cudaEventDestroy(e_ms);
    cudaStreamDestroy(s2);
    cudaStreamDestroy(s3);
}